// round 4
// baseline (speedup 1.0000x reference)
#include <cuda_runtime.h>
#include <cuda_bf16.h>
#include <cstdint>

#define N_NODES 90000
#define N_EDGES 540000
#define IN_F    30
#define N_GRAPH 10000

// ======================= global scratch =======================
__device__ __nv_bfloat16 g_agg0_h[N_NODES * 32];
__device__ __nv_bfloat16 g_agg0_l[N_NODES * 32];
__device__ __nv_bfloat16 g_agg1_h[N_NODES * 128];
__device__ __nv_bfloat16 g_agg1_l[N_NODES * 128];
__device__ float g_z1s[N_NODES * 128];
__device__ float g_z1t[N_NODES * 128];
__device__ float g_z2s[N_NODES * 64];
__device__ float g_z2t[N_NODES * 64];
__device__ __nv_bfloat16 g_pwh[2][4][128 * 128];   // prepared weights [branch][layer][n][k]
__device__ __nv_bfloat16 g_pwl[2][4][128 * 128];
__device__ int g_deg[N_NODES];
__device__ int g_cursor[N_NODES];
__device__ int g_rowptr[N_NODES + 1];
__device__ int g_csrsrc[N_EDGES];

__device__ __forceinline__ void bf16_split(float v, __nv_bfloat16& h, __nv_bfloat16& l) {
    h = __float2bfloat16(v);
    l = __float2bfloat16(v - __bfloat162float(h));
}
__device__ __forceinline__ void split_pack(float v0, float v1, uint32_t& hi, uint32_t& lo) {
    __nv_bfloat16 h0, l0, h1, l1;
    bf16_split(v0, h0, l0);
    bf16_split(v1, h1, l1);
    __nv_bfloat162 ph; ph.x = h0; ph.y = h1;
    __nv_bfloat162 pl; pl.x = l0; pl.y = l1;
    hi = *(uint32_t*)&ph; lo = *(uint32_t*)&pl;
}

// bf16 tensor-core MMA, fp32 accumulate (family-portable, sm_80+)
__device__ __forceinline__ void mma16816(float* d, const uint32_t* a, const uint32_t* b) {
    asm volatile(
        "mma.sync.aligned.m16n8k16.row.col.f32.bf16.bf16.f32 "
        "{%0,%1,%2,%3}, {%4,%5,%6,%7}, {%8,%9}, {%0,%1,%2,%3};\n"
        : "+f"(d[0]), "+f"(d[1]), "+f"(d[2]), "+f"(d[3])
        : "r"(a[0]), "r"(a[1]), "r"(a[2]), "r"(a[3]), "r"(b[0]), "r"(b[1]));
}

// ======================= CSR build =======================
__global__ void zero_kernel() {
    int i = blockIdx.x * blockDim.x + threadIdx.x;
    if (i < N_NODES) { g_deg[i] = 0; g_cursor[i] = 0; }
}
__global__ void hist_kernel(const int* __restrict__ ei) {
    int e = blockIdx.x * blockDim.x + threadIdx.x;
    if (e < N_EDGES) atomicAdd(&g_deg[ei[N_EDGES + e]], 1);
}
__global__ void scan_kernel() {
    const int CHUNK = (N_NODES + 1023) / 1024;
    __shared__ int part[1024];
    int t = threadIdx.x;
    int start = t * CHUNK;
    int s = 0;
    for (int i = 0; i < CHUNK; i++) {
        int idx = start + i;
        if (idx < N_NODES) s += g_deg[idx];
    }
    part[t] = s;
    __syncthreads();
    for (int off = 1; off < 1024; off <<= 1) {
        int v = (t >= off) ? part[t - off] : 0;
        __syncthreads();
        part[t] += v;
        __syncthreads();
    }
    int run = (t > 0) ? part[t - 1] : 0;
    for (int i = 0; i < CHUNK; i++) {
        int idx = start + i;
        if (idx < N_NODES) { g_rowptr[idx] = run; run += g_deg[idx]; }
    }
    if (t == 1023) g_rowptr[N_NODES] = part[1023];
}
__global__ void fill_kernel(const int* __restrict__ ei) {
    int e = blockIdx.x * blockDim.x + threadIdx.x;
    if (e < N_EDGES) {
        int src = ei[e];
        int dst = ei[N_EDGES + e];
        int pos = g_rowptr[dst] + atomicAdd(&g_cursor[dst], 1);
        g_csrsrc[pos] = src;
    }
}

// ======================= weight prep: W[K x N] fp32 -> [n][k] bf16 hi/lo (transposed, K padded)
__global__ void prep_kernel(const float* __restrict__ W, int Kreal, int Nout, int br, int li) {
    int n = blockIdx.x;
    int k = threadIdx.x;
    int Ksm = blockDim.x;
    float v = (k < Kreal) ? W[k * Nout + n] : 0.f;
    __nv_bfloat16 h, l;
    bf16_split(v, h, l);
    g_pwh[br][li][n * Ksm + k] = h;
    g_pwl[br][li][n * Ksm + k] = l;
}

// ======================= layer-1 aggregation -> bf16 hi/lo, K padded to 32
__global__ void agg0_kernel(const float* __restrict__ x) {
    int w = (blockIdx.x * blockDim.x + threadIdx.x) >> 5;
    int lane = threadIdx.x & 31;
    if (w >= N_NODES) return;
    float acc = (lane < IN_F) ? x[w * IN_F + lane] : 0.f;
    int s0 = g_rowptr[w], s1 = g_rowptr[w + 1];
    for (int e = s0; e < s1; e++) {
        int s = g_csrsrc[e];
        if (lane < IN_F) acc += x[s * IN_F + lane];
    }
    __nv_bfloat16 h, l;
    bf16_split(acc, h, l);
    g_agg0_h[w * 32 + lane] = h;
    g_agg0_l[w * 32 + lane] = l;
}

// ======================= layer-2 aggregation: z1 fp32 -> agg1 bf16 hi/lo
__global__ void agg1_kernel(int br) {
    const float4* z = (const float4*)(br ? g_z1t : g_z1s);
    int w = (blockIdx.x * blockDim.x + threadIdx.x) >> 5;
    int lane = threadIdx.x & 31;
    if (w >= N_NODES) return;
    float4 acc = z[w * 32 + lane];
    int s0 = g_rowptr[w], s1 = g_rowptr[w + 1];
    for (int e = s0; e < s1; e++) {
        int s = g_csrsrc[e];
        float4 v = z[s * 32 + lane];
        acc.x += v.x; acc.y += v.y; acc.z += v.z; acc.w += v.w;
    }
    uint32_t h01, l01, h23, l23;
    split_pack(acc.x, acc.y, h01, l01);
    split_pack(acc.z, acc.w, h23, l23);
    uint32_t* oh = (uint32_t*)(g_agg1_h + (size_t)w * 128 + lane * 4);
    uint32_t* ol = (uint32_t*)(g_agg1_l + (size_t)w * 128 + lane * 4);
    oh[0] = h01; oh[1] = h23;
    ol[0] = l01; ol[1] = l23;
}

// ======================= fused 2-layer MLP via mma.sync =======================
// pass1: H = relu(A[128 x K1] @ W1^T + b1)  -> smem (bf16 hi/lo)
// pass2: Z = H[128 x 128] @ W2^T + b2       -> global fp32
// split precision: D = Ah*Bh + Ah*Bl + Al*Bh
template<int K1, int NT2>
__global__ __launch_bounds__(256) void mlp_kernel(int a_sel, int br, int out_sel,
                                                  const float* __restrict__ b1,
                                                  const float* __restrict__ b2)
{
    constexpr int PK1 = K1 + 8;
    constexpr int PK2 = 136;             // 128 + 8
    constexpr int TILEH = 128 * PK2;     // halfs per buffer
    constexpr int NOUT2 = NT2 * 16;      // 128 or 64
    extern __shared__ char smraw[];
    __nv_bfloat16* AH = (__nv_bfloat16*)smraw;     // A tile, then H tile
    __nv_bfloat16* AL = AH + TILEH;
    __nv_bfloat16* WH = AL + TILEH;                // W1 tile, then W2 tile
    __nv_bfloat16* WL = WH + TILEH;

    int tid = threadIdx.x, lane = tid & 31, wid = tid >> 5;
    int warpM = wid & 3, warpN = wid >> 2;
    int row0 = blockIdx.x * 128;
    int lg = lane >> 2;        // groupID (0..7)
    int lt = lane & 3;         // thread-in-group

    const __nv_bfloat16* Agh = a_sel ? g_agg1_h : g_agg0_h;
    const __nv_bfloat16* Agl = a_sel ? g_agg1_l : g_agg0_l;
    int l1 = a_sel ? 2 : 0;
    const __nv_bfloat16* W1h = g_pwh[br][l1];
    const __nv_bfloat16* W1l = g_pwl[br][l1];
    const __nv_bfloat16* W2h = g_pwh[br][l1 + 1];
    const __nv_bfloat16* W2l = g_pwl[br][l1 + 1];

    // ---- load A (K1 wide) and W1 into smem (pitch PK1, pad zeroed) ----
    {
        constexpr int CPR = PK1 / 8;
        for (int i = tid; i < 128 * CPR; i += 256) {
            int r = i / CPR, c = i % CPR, col = c * 8;
            float4 zf = make_float4(0.f, 0.f, 0.f, 0.f);
            float4 vh = zf, vl = zf, wh = zf, wl = zf;
            int gr = row0 + r;
            if (col < K1) {
                if (gr < N_NODES) {
                    vh = *(const float4*)(Agh + (size_t)gr * K1 + col);
                    vl = *(const float4*)(Agl + (size_t)gr * K1 + col);
                }
                wh = *(const float4*)(W1h + r * K1 + col);
                wl = *(const float4*)(W1l + r * K1 + col);
            }
            *(float4*)(AH + r * PK1 + col) = vh;
            *(float4*)(AL + r * PK1 + col) = vl;
            *(float4*)(WH + r * PK1 + col) = wh;
            *(float4*)(WL + r * PK1 + col) = wl;
        }
    }
    __syncthreads();

    // ---- pass 1: 128 x 128, warp tile 32 x 64 ----
    float acc[2][8][4];
    #pragma unroll
    for (int tm = 0; tm < 2; tm++)
        #pragma unroll
        for (int tn = 0; tn < 8; tn++)
            #pragma unroll
            for (int q = 0; q < 4; q++) acc[tm][tn][q] = 0.f;

    #pragma unroll
    for (int ks = 0; ks < K1 / 16; ks++) {
        int k0 = ks * 16 + lt * 2;
        uint32_t ah[2][4], al[2][4];
        #pragma unroll
        for (int tm = 0; tm < 2; tm++) {
            int r = warpM * 32 + tm * 16 + lg;
            ah[tm][0] = *(const uint32_t*)(AH + r * PK1 + k0);
            ah[tm][1] = *(const uint32_t*)(AH + (r + 8) * PK1 + k0);
            ah[tm][2] = *(const uint32_t*)(AH + r * PK1 + k0 + 8);
            ah[tm][3] = *(const uint32_t*)(AH + (r + 8) * PK1 + k0 + 8);
            al[tm][0] = *(const uint32_t*)(AL + r * PK1 + k0);
            al[tm][1] = *(const uint32_t*)(AL + (r + 8) * PK1 + k0);
            al[tm][2] = *(const uint32_t*)(AL + r * PK1 + k0 + 8);
            al[tm][3] = *(const uint32_t*)(AL + (r + 8) * PK1 + k0 + 8);
        }
        #pragma unroll
        for (int tn = 0; tn < 8; tn++) {
            int n = warpN * 64 + tn * 8 + lg;
            uint32_t bh[2], bl[2];
            bh[0] = *(const uint32_t*)(WH + n * PK1 + k0);
            bh[1] = *(const uint32_t*)(WH + n * PK1 + k0 + 8);
            bl[0] = *(const uint32_t*)(WL + n * PK1 + k0);
            bl[1] = *(const uint32_t*)(WL + n * PK1 + k0 + 8);
            #pragma unroll
            for (int tm = 0; tm < 2; tm++) {
                mma16816(acc[tm][tn], ah[tm], bh);
                mma16816(acc[tm][tn], ah[tm], bl);
                mma16816(acc[tm][tn], al[tm], bh);
            }
        }
    }
    __syncthreads();   // done reading A/W1

    // ---- stage H = relu(acc + b1) -> smem (split hi/lo), pitch PK2 ----
    #pragma unroll
    for (int tm = 0; tm < 2; tm++) {
        int m = warpM * 32 + tm * 16 + lg;
        #pragma unroll
        for (int tn = 0; tn < 8; tn++) {
            int n = warpN * 64 + tn * 8 + lt * 2;
            float2 bv = *(const float2*)(b1 + n);
            float v0 = fmaxf(acc[tm][tn][0] + bv.x, 0.f);
            float v1 = fmaxf(acc[tm][tn][1] + bv.y, 0.f);
            float v2 = fmaxf(acc[tm][tn][2] + bv.x, 0.f);
            float v3 = fmaxf(acc[tm][tn][3] + bv.y, 0.f);
            uint32_t hi, lo;
            split_pack(v0, v1, hi, lo);
            *(uint32_t*)(AH + m * PK2 + n) = hi;
            *(uint32_t*)(AL + m * PK2 + n) = lo;
            split_pack(v2, v3, hi, lo);
            *(uint32_t*)(AH + (m + 8) * PK2 + n) = hi;
            *(uint32_t*)(AL + (m + 8) * PK2 + n) = lo;
        }
    }
    // ---- load W2 (NOUT2 rows x 128) into W region ----
    for (int i = tid; i < NOUT2 * 17; i += 256) {
        int r = i / 17, c = i % 17, col = c * 8;
        float4 wh = make_float4(0.f, 0.f, 0.f, 0.f), wl = wh;
        if (col < 128) {
            wh = *(const float4*)(W2h + r * 128 + col);
            wl = *(const float4*)(W2l + r * 128 + col);
        }
        *(float4*)(WH + r * PK2 + col) = wh;
        *(float4*)(WL + r * PK2 + col) = wl;
    }
    __syncthreads();

    // ---- pass 2: 128 x NOUT2, K=128 ----
    float acc2[2][NT2][4];
    #pragma unroll
    for (int tm = 0; tm < 2; tm++)
        #pragma unroll
        for (int tn = 0; tn < NT2; tn++)
            #pragma unroll
            for (int q = 0; q < 4; q++) acc2[tm][tn][q] = 0.f;

    #pragma unroll
    for (int ks = 0; ks < 8; ks++) {
        int k0 = ks * 16 + lt * 2;
        uint32_t ah[2][4], al[2][4];
        #pragma unroll
        for (int tm = 0; tm < 2; tm++) {
            int r = warpM * 32 + tm * 16 + lg;
            ah[tm][0] = *(const uint32_t*)(AH + r * PK2 + k0);
            ah[tm][1] = *(const uint32_t*)(AH + (r + 8) * PK2 + k0);
            ah[tm][2] = *(const uint32_t*)(AH + r * PK2 + k0 + 8);
            ah[tm][3] = *(const uint32_t*)(AH + (r + 8) * PK2 + k0 + 8);
            al[tm][0] = *(const uint32_t*)(AL + r * PK2 + k0);
            al[tm][1] = *(const uint32_t*)(AL + (r + 8) * PK2 + k0);
            al[tm][2] = *(const uint32_t*)(AL + r * PK2 + k0 + 8);
            al[tm][3] = *(const uint32_t*)(AL + (r + 8) * PK2 + k0 + 8);
        }
        #pragma unroll
        for (int tn = 0; tn < NT2; tn++) {
            int n = warpN * (NOUT2 / 2) + tn * 8 + lg;
            uint32_t bh[2], bl[2];
            bh[0] = *(const uint32_t*)(WH + n * PK2 + k0);
            bh[1] = *(const uint32_t*)(WH + n * PK2 + k0 + 8);
            bl[0] = *(const uint32_t*)(WL + n * PK2 + k0);
            bl[1] = *(const uint32_t*)(WL + n * PK2 + k0 + 8);
            #pragma unroll
            for (int tm = 0; tm < 2; tm++) {
                mma16816(acc2[tm][tn], ah[tm], bh);
                mma16816(acc2[tm][tn], ah[tm], bl);
                mma16816(acc2[tm][tn], al[tm], bh);
            }
        }
    }

    // ---- epilogue: Z + b2 -> global fp32 ----
    float* outF = (out_sel == 0) ? g_z1s : (out_sel == 1) ? g_z1t
                 : (out_sel == 2) ? g_z2s : g_z2t;
    #pragma unroll
    for (int tm = 0; tm < 2; tm++) {
        int m = warpM * 32 + tm * 16 + lg;
        #pragma unroll
        for (int tn = 0; tn < NT2; tn++) {
            int n = warpN * (NOUT2 / 2) + tn * 8 + lt * 2;
            float2 bv = *(const float2*)(b2 + n);
            int g0 = row0 + m;
            if (g0 < N_NODES) {
                float2 o; o.x = acc2[tm][tn][0] + bv.x; o.y = acc2[tm][tn][1] + bv.y;
                *(float2*)(outF + (size_t)g0 * NOUT2 + n) = o;
            }
            int g1 = row0 + m + 8;
            if (g1 < N_NODES) {
                float2 o; o.x = acc2[tm][tn][2] + bv.x; o.y = acc2[tm][tn][3] + bv.y;
                *(float2*)(outF + (size_t)g1 * NOUT2 + n) = o;
            }
        }
    }
}

// ======================= per-graph 9x9 gram =======================
__global__ void final_kernel(float* __restrict__ out) {
    __shared__ float zs[9 * 64];
    __shared__ float zt[9 * 64];
    int g = blockIdx.x;
    const float4* ps = (const float4*)(g_z2s + (size_t)g * 9 * 64);
    const float4* pt = (const float4*)(g_z2t + (size_t)g * 9 * 64);
    int tid = threadIdx.x;
    for (int i = tid; i < 144; i += 128) {
        ((float4*)zs)[i] = ps[i];
        ((float4*)zt)[i] = pt[i];
    }
    __syncthreads();
    if (tid < 81) {
        int i = tid / 9, j = tid % 9;
        float acc = 0.f;
        #pragma unroll
        for (int k = 0; k < 64; k++) acc += zs[i * 64 + k] * zt[j * 64 + k];
        out[(g * 9 + i) * 9 + j] = acc;
    }
}

// ======================= launch =======================
extern "C" void kernel_launch(void* const* d_in, const int* in_sizes, int n_in,
                              void* d_out, int out_size) {
    const float* x  = (const float*)d_in[0];
    const int*   ei = (const int*)d_in[1];
    const float* W[2][4] = {
        { (const float*)d_in[2],  (const float*)d_in[4],  (const float*)d_in[6],  (const float*)d_in[8]  },
        { (const float*)d_in[10], (const float*)d_in[12], (const float*)d_in[14], (const float*)d_in[16] }
    };
    const float* B[2][4] = {
        { (const float*)d_in[3],  (const float*)d_in[5],  (const float*)d_in[7],  (const float*)d_in[9]  },
        { (const float*)d_in[11], (const float*)d_in[13], (const float*)d_in[15], (const float*)d_in[17] }
    };
    float* out = (float*)d_out;

    const int SMEM = 4 * 128 * 136 * 2;   // 139264 bytes
    cudaFuncSetAttribute(mlp_kernel<32, 8>,  cudaFuncAttributeMaxDynamicSharedMemorySize, SMEM);
    cudaFuncSetAttribute(mlp_kernel<128, 4>, cudaFuncAttributeMaxDynamicSharedMemorySize, SMEM);

    const int GEMM_BLOCKS = (N_NODES + 127) / 128;       // 704
    const int WARP_BLOCKS = (N_NODES * 32 + 255) / 256;

    // CSR build
    zero_kernel<<<(N_NODES + 255) / 256, 256>>>();
    hist_kernel<<<(N_EDGES + 255) / 256, 256>>>(ei);
    scan_kernel<<<1, 1024>>>();
    fill_kernel<<<(N_EDGES + 255) / 256, 256>>>(ei);

    // weight prep
    for (int br = 0; br < 2; br++) {
        prep_kernel<<<128, 32>>>(W[br][0], IN_F, 128, br, 0);   // W1: 30x128 -> K_SMEM=32
        prep_kernel<<<128, 128>>>(W[br][1], 128, 128, br, 1);
        prep_kernel<<<128, 128>>>(W[br][2], 128, 128, br, 2);
        prep_kernel<<<64, 128>>>(W[br][3], 128, 64, br, 3);
    }

    agg0_kernel<<<WARP_BLOCKS, 256>>>(x);

    // layer 1 (fused MLP), both branches
    mlp_kernel<32, 8><<<GEMM_BLOCKS, 256, SMEM>>>(0, 0, 0, B[0][0], B[0][1]);
    mlp_kernel<32, 8><<<GEMM_BLOCKS, 256, SMEM>>>(0, 1, 1, B[1][0], B[1][1]);

    // layer 2 (agg + fused MLP), both branches
    agg1_kernel<<<WARP_BLOCKS, 256>>>(0);
    mlp_kernel<128, 4><<<GEMM_BLOCKS, 256, SMEM>>>(1, 0, 2, B[0][2], B[0][3]);
    agg1_kernel<<<WARP_BLOCKS, 256>>>(1);
    mlp_kernel<128, 4><<<GEMM_BLOCKS, 256, SMEM>>>(1, 1, 3, B[1][2], B[1][3]);

    final_kernel<<<N_GRAPH, 128>>>(out);
}